// round 2
// baseline (speedup 1.0000x reference)
#include <cuda_runtime.h>
#include <math.h>

#define T_ 256
#define B_ 128
#define H_ 1024
#define L_ 4
#define TB_ (T_ * B_)        /* 32768 */
#define BH_ (B_ * H_)        /* 131072 */
#define TBH_ (T_ * B_ * H_)  /* 33554432 */

#define REC_CTAS 128         /* must be <= 148 so all CTAs co-resident */

// Ping-pong full-sequence scratch (134MB each). Allocation-free per rules.
__device__ float g_seq0[TBH_];
__device__ float g_seq1[TBH_];

// Grid-barrier state (monotonic generation; count resets each barrier).
__device__ unsigned int g_cnt = 0;
__device__ unsigned int g_gen = 0;

// ---------------------------------------------------------------------------
// Input projection GEMM: out[m, n] = sum_k X[m,k] * W[n,k] + bi[n] + bh[n]
// M = TB_ (32768), N = H_ (1024), K = H_ (1024). NT layout.
// Tile 128x128, BK=8, 256 threads, 8x8 per thread.
// ---------------------------------------------------------------------------
__global__ __launch_bounds__(256)
void proj_kernel(const float* __restrict__ X,
                 const float* __restrict__ W,
                 const float* __restrict__ bi,
                 const float* __restrict__ bh,
                 float* __restrict__ out)
{
    __shared__ float As[8][128];
    __shared__ float Bs[8][128];

    const int tid = threadIdx.x;
    const int m0 = blockIdx.y * 128;
    const int n0 = blockIdx.x * 128;

    const int lr = tid >> 1;           // 0..127
    const int lk = (tid & 1) * 4;      // 0 or 4

    const float* Ag = X + (size_t)(m0 + lr) * H_ + lk;
    const float* Bg = W + (size_t)(n0 + lr) * H_ + lk;

    const int ty = tid >> 4;
    const int tx = tid & 15;

    float acc[8][8];
#pragma unroll
    for (int i = 0; i < 8; i++)
#pragma unroll
        for (int j = 0; j < 8; j++) acc[i][j] = 0.0f;

    for (int kt = 0; kt < H_; kt += 8) {
        float4 a4 = *(const float4*)(Ag + kt);
        float4 b4 = *(const float4*)(Bg + kt);
        __syncthreads();
        As[lk + 0][lr] = a4.x; As[lk + 1][lr] = a4.y;
        As[lk + 2][lr] = a4.z; As[lk + 3][lr] = a4.w;
        Bs[lk + 0][lr] = b4.x; Bs[lk + 1][lr] = b4.y;
        Bs[lk + 2][lr] = b4.z; Bs[lk + 3][lr] = b4.w;
        __syncthreads();
#pragma unroll
        for (int k = 0; k < 8; k++) {
            float a[8], b[8];
#pragma unroll
            for (int i = 0; i < 8; i++) a[i] = As[k][ty * 8 + i];
#pragma unroll
            for (int j = 0; j < 8; j++) b[j] = Bs[k][tx * 8 + j];
#pragma unroll
            for (int i = 0; i < 8; i++)
#pragma unroll
                for (int j = 0; j < 8; j++)
                    acc[i][j] = fmaf(a[i], b[j], acc[i][j]);
        }
    }

    const int nbase = n0 + tx * 8;
    float bias[8];
#pragma unroll
    for (int j = 0; j < 8; j++) bias[j] = bi[nbase + j] + bh[nbase + j];

#pragma unroll
    for (int i = 0; i < 8; i++) {
        const int m = m0 + ty * 8 + i;
        float* orow = out + (size_t)m * H_ + nbase;
        float4 v0, v1;
        v0.x = acc[i][0] + bias[0]; v0.y = acc[i][1] + bias[1];
        v0.z = acc[i][2] + bias[2]; v0.w = acc[i][3] + bias[3];
        v1.x = acc[i][4] + bias[4]; v1.y = acc[i][5] + bias[5];
        v1.z = acc[i][6] + bias[6]; v1.w = acc[i][7] + bias[7];
        *(float4*)(orow)     = v0;
        *(float4*)(orow + 4) = v1;
    }
}

// ---------------------------------------------------------------------------
// Persistent recurrence for one layer: loops over all T steps with a software
// grid barrier. Grid MUST be REC_CTAS (=128) CTAs of 128 threads -> all
// co-resident on 148 SMs, so the spin barrier cannot deadlock.
//
// Step t: Y[t][b, j] = tanh(Y[t][b, j] + sum_k h_{t-1}[b,k] * Wh[j,k])
// where h_{t-1} = Y[t-1] (or hx for t=0). Tile BM=16, BN=64, BK=64.
// Each CTA owns a fixed (m0, n0) tile across all timesteps.
// ---------------------------------------------------------------------------
__global__ __launch_bounds__(128)
void recur_kernel(const float* __restrict__ hx,   // [B, H] initial hidden
                  const float* __restrict__ W,    // [H, H] W_hh
                  float* __restrict__ Y,          // [T, B, H] proj in, h out
                  float* __restrict__ hn)         // [B, H] final hidden out
{
    __shared__ float As[64][17];
    __shared__ float Bs[64][65];
    __shared__ unsigned int s_gen;

    const int tid = threadIdx.x;
    const int n0 = blockIdx.x * 64;
    const int m0 = blockIdx.y * 16;

    // Entry generation snapshot (stable: all CTAs read before any first-arrive).
    if (tid == 0) s_gen = atomicAdd(&g_gen, 0u);
    __syncthreads();
    const unsigned int gen0 = s_gen;

    const int ar = tid >> 4;          // 0..7
    const int ac = (tid & 15) * 4;    // 0,4,...,60
    const int r0 = (tid >> 4) * 2;
    const int c0 = (tid & 15) * 4;

    for (int t = 0; t < T_; t++) {
        const float* hp = (t == 0) ? hx : (Y + (size_t)(t - 1) * BH_);
        float* yt = Y + (size_t)t * BH_;

        float acc[2][4];
#pragma unroll
        for (int i = 0; i < 2; i++)
#pragma unroll
            for (int j = 0; j < 4; j++) acc[i][j] = 0.0f;

        for (int kt = 0; kt < H_; kt += 64) {
            float4 a0 = *(const float4*)(hp + (size_t)(m0 + ar) * H_ + kt + ac);
            float4 a1 = *(const float4*)(hp + (size_t)(m0 + ar + 8) * H_ + kt + ac);
            float4 bv[8];
#pragma unroll
            for (int i = 0; i < 8; i++) {
                const int jr = (tid >> 4) * 8 + i;
                bv[i] = *(const float4*)(W + (size_t)(n0 + jr) * H_ + kt + ac);
            }
            __syncthreads();
            As[ac + 0][ar] = a0.x; As[ac + 1][ar] = a0.y;
            As[ac + 2][ar] = a0.z; As[ac + 3][ar] = a0.w;
            As[ac + 0][ar + 8] = a1.x; As[ac + 1][ar + 8] = a1.y;
            As[ac + 2][ar + 8] = a1.z; As[ac + 3][ar + 8] = a1.w;
#pragma unroll
            for (int i = 0; i < 8; i++) {
                const int jr = (tid >> 4) * 8 + i;
                Bs[ac + 0][jr] = bv[i].x; Bs[ac + 1][jr] = bv[i].y;
                Bs[ac + 2][jr] = bv[i].z; Bs[ac + 3][jr] = bv[i].w;
            }
            __syncthreads();

#pragma unroll 8
            for (int k = 0; k < 64; k++) {
                const float av0 = As[k][r0];
                const float av1 = As[k][r0 + 1];
                float b0 = Bs[k][c0 + 0];
                float b1 = Bs[k][c0 + 1];
                float b2 = Bs[k][c0 + 2];
                float b3 = Bs[k][c0 + 3];
                acc[0][0] = fmaf(av0, b0, acc[0][0]);
                acc[0][1] = fmaf(av0, b1, acc[0][1]);
                acc[0][2] = fmaf(av0, b2, acc[0][2]);
                acc[0][3] = fmaf(av0, b3, acc[0][3]);
                acc[1][0] = fmaf(av1, b0, acc[1][0]);
                acc[1][1] = fmaf(av1, b1, acc[1][1]);
                acc[1][2] = fmaf(av1, b2, acc[1][2]);
                acc[1][3] = fmaf(av1, b3, acc[1][3]);
            }
        }

        // Epilogue: add precomputed projection (in place) and tanh.
#pragma unroll
        for (int i = 0; i < 2; i++) {
            const int b = m0 + r0 + i;
            float* orow = yt + (size_t)b * H_ + n0 + c0;
            float4 p = *(const float4*)orow;
            float4 v;
            v.x = tanhf(acc[i][0] + p.x);
            v.y = tanhf(acc[i][1] + p.y);
            v.z = tanhf(acc[i][2] + p.z);
            v.w = tanhf(acc[i][3] + p.w);
            *(float4*)orow = v;
            if (t == T_ - 1) *(float4*)(hn + (size_t)b * H_ + n0 + c0) = v;
        }

        // ---- grid barrier: all CTAs finished step t before step t+1 reads it
        __syncthreads();
        if (tid == 0) {
            __threadfence();                                  // release h_t
            unsigned int old = atomicAdd(&g_cnt, 1u);
            if (old == REC_CTAS - 1) {
                atomicExch(&g_cnt, 0u);                       // reset for next
                __threadfence();
                atomicAdd(&g_gen, 1u);                        // open the gate
            } else {
                const unsigned int target = gen0 + (unsigned int)t + 1u;
                while (atomicAdd(&g_gen, 0u) < target) { }
            }
            __threadfence();                                  // acquire h_t
        }
        __syncthreads();
    }
}

// ---------------------------------------------------------------------------
extern "C" void kernel_launch(void* const* d_in, const int* in_sizes, int n_in,
                              void* d_out, int out_size)
{
    const float* inputs = (const float*)d_in[0];  // [T, B, H]
    const float* hxs    = (const float*)d_in[1];  // [L, B, H]
    const float* W_ih   = (const float*)d_in[2];  // [L, H, H]
    const float* b_ih   = (const float*)d_in[3];  // [L, H]
    const float* W_hh   = (const float*)d_in[4];  // [L, H, H]
    const float* b_hh   = (const float*)d_in[5];  // [L, H]
    float* out = (float*)d_out;                   // [x (T,B,H); hns (L,B,H)]

    float* seq0 = nullptr;
    float* seq1 = nullptr;
    cudaGetSymbolAddress((void**)&seq0, g_seq0);
    cudaGetSymbolAddress((void**)&seq1, g_seq1);

    // Layer buffer schedule: l0 -> seq0, l1 -> seq1, l2 -> seq0, l3 -> out(x)
    const float* layer_in[L_]  = { inputs, seq0, seq1, seq0 };
    float*       layer_out[L_] = { seq0, seq1, seq0, out };

    const dim3 proj_grid(H_ / 128, TB_ / 128);   // (8, 256)
    const dim3 rec_grid(H_ / 64, B_ / 16);       // (16, 8) = 128 CTAs

    for (int l = 0; l < L_; l++) {
        const float* X = layer_in[l];
        float* Y = layer_out[l];
        const float* Wi = W_ih + (size_t)l * H_ * H_;
        const float* Wh = W_hh + (size_t)l * H_ * H_;
        const float* bi = b_ih + (size_t)l * H_;
        const float* bh = b_hh + (size_t)l * H_;

        // Batched input projection for all T timesteps (into Y).
        proj_kernel<<<proj_grid, 256>>>(X, Wi, bi, bh, Y);

        // Entire recurrence for this layer in one persistent launch.
        recur_kernel<<<rec_grid, 128>>>(hxs + (size_t)l * BH_, Wh, Y,
                                        out + (size_t)TBH_ + (size_t)l * BH_);
    }
}